// round 15
// baseline (speedup 1.0000x reference)
#include <cuda_runtime.h>
#include <cuda_fp16.h>
#include <math.h>

#define DIMZ 128
#define HW   (128*128)
#define VOL  (128*128*128)
#define NB   2
#define NK   4
#define RAD  4
#define ZC   32                 // z-chunk in K2 (halo ratio 1.25)
#define K2_CTAS (16*4*8)        // ytiles * zchunks * (k*b)

// 32 MB fp16 scratch for the XY-blurred labels field.
__device__ __align__(16) __half g_blur[NB*NK*VOL];

struct Scal {
    float  S1[NB*NK];
    float  S2[NB*NK];
    double num[NK];
    double den[NK];
    int    ctr;
};
__device__ Scal g_s;

// gauss taps: exp(-x^2/(2*25)) for x=-4..4 (fp32, for x-blur + packing)
__constant__ float c_g[9] = {
    0.72614904f, 0.83527021f, 0.92311635f, 0.98019867f, 1.0f,
    0.98019867f, 0.92311635f, 0.83527021f, 0.72614904f
};
// same taps as packed half2 bit patterns (round-to-nearest fp16)
__constant__ unsigned c_gh2[9] = {
    0x39CF39CFu, 0x3AAF3AAFu, 0x3B633B63u, 0x3BD73BD7u, 0x3C003C00u,
    0x3BD73BD7u, 0x3B633B63u, 0x3AAF3AAFu, 0x39CF39CFu
};

__device__ __forceinline__ __half2 u2h(unsigned u) {
    return *reinterpret_cast<__half2*>(&u);
}
__device__ __forceinline__ unsigned h2u(__half2 h) {
    return *reinterpret_cast<unsigned*>(&h);
}

__device__ __forceinline__ float blur9(const float* a) {
    float acc = 0.f;
    #pragma unroll
    for (int t = 0; t < 9; t++) acc = fmaf(c_g[t], a[t], acc);
    return acc;
}

// Load labels row gy (zero outside volume), accumulate mean sums on uniquely
// owned center rows, return the X-blurred float4 for this lane (x = 4*lane)
// using lane shuffles for the +-4 halo. No shared memory.
__device__ __forceinline__ float4 xblur_load(
    int gy, const float4* __restrict__ lp4, const float4* __restrict__ ip4,
    int lane, int y0, float& s1, float& s2)
{
    float4 c = make_float4(0.f, 0.f, 0.f, 0.f);
    if (gy >= 0 && gy < 128) {
        c = __ldcs(lp4 + gy * 32 + lane);
        if (gy >= y0 && gy < y0 + 32) {
            float4 u = ip4[gy * 32 + lane];
            s1 += c.x*u.x + c.y*u.y + c.z*u.z + c.w*u.w;
            s2 += c.x + c.y + c.z + c.w;
        }
    }
    float a[12];
    a[0] = __shfl_up_sync(0xffffffffu, c.x, 1);
    a[1] = __shfl_up_sync(0xffffffffu, c.y, 1);
    a[2] = __shfl_up_sync(0xffffffffu, c.z, 1);
    a[3] = __shfl_up_sync(0xffffffffu, c.w, 1);
    if (lane == 0) { a[0] = a[1] = a[2] = a[3] = 0.f; }
    a[4] = c.x; a[5] = c.y; a[6] = c.z; a[7] = c.w;
    a[8]  = __shfl_down_sync(0xffffffffu, c.x, 1);
    a[9]  = __shfl_down_sync(0xffffffffu, c.y, 1);
    a[10] = __shfl_down_sync(0xffffffffu, c.z, 1);
    a[11] = __shfl_down_sync(0xffffffffu, c.w, 1);
    if (lane == 31) { a[8] = a[9] = a[10] = a[11] = 0.f; }
    float4 r;
    r.x = blur9(a + 0);
    r.y = blur9(a + 1);
    r.z = blur9(a + 2);
    r.w = blur9(a + 3);
    return r;
}

// Pack an fp32 x-blurred float4 into 2 half2 (uint2).
__device__ __forceinline__ uint2 pack4(float4 r) {
    uint2 p;
    p.x = h2u(__floats2half2_rn(r.x, r.y));
    p.y = h2u(__floats2half2_rn(r.z, r.w));
    return p;
}

// ---------------------------------------------------------------------------
// K1: XY blur of labels (R12 body/shape — best measured; untouched).
// CTA = 128 thr = 4 warps = 4 y-quarters of ONE z-slice.
// grid: (128 z, 4 k, 2 b) = 1024 CTAs.
// ---------------------------------------------------------------------------
__global__ __launch_bounds__(128)
void k_xyblur(const float* __restrict__ labels, const float* __restrict__ inputs) {
    const int tid = threadIdx.x;
    const int warp = tid >> 5, lane = tid & 31;
    const int z  = blockIdx.x;
    const int y0 = warp * 32;
    const int k  = blockIdx.y;
    const int b  = blockIdx.z;
    const int x4 = lane * 4;

    const float4* lp4 = (const float4*)(labels + (size_t)(b*NK + k) * VOL + (size_t)z * HW);
    const float4* ip4 = (const float4*)(inputs + (size_t)b * VOL + (size_t)z * HW);
    __half* op = g_blur + (size_t)(b*NK + k) * VOL + (size_t)z * HW;

    float s1 = 0.f, s2 = 0.f;
    uint2 w[9];
    #pragma unroll
    for (int j = 0; j < 9; j++)
        w[j] = pack4(xblur_load(y0 - RAD + j, lp4, ip4, lane, y0, s1, s2));

    #pragma unroll 4
    for (int i = 0; i < 32; i++) {
        __half2 b0 = u2h(0u), b1 = u2h(0u);
        #pragma unroll
        for (int j = 0; j < 9; j++) {
            __half2 g = u2h(c_gh2[j]);
            b0 = __hfma2(g, u2h(w[j].x), b0);
            b1 = __hfma2(g, u2h(w[j].y), b1);
        }
        uint2 pk; pk.x = h2u(b0); pk.y = h2u(b1);
        *reinterpret_cast<uint2*>(op + (y0 + i) * 128 + x4) = pk;

        #pragma unroll
        for (int j = 0; j < 8; j++) w[j] = w[j + 1];
        w[8] = pack4(xblur_load(y0 + i + RAD + 1, lp4, ip4, lane, y0, s1, s2));
    }

    #pragma unroll
    for (int o = 16; o; o >>= 1) {
        s1 += __shfl_down_sync(0xffffffffu, s1, o);
        s2 += __shfl_down_sync(0xffffffffu, s2, o);
    }
    __shared__ float rs1[4], rs2[4];
    if (lane == 0) { rs1[warp] = s1; rs2[warp] = s2; }
    __syncthreads();
    if (tid == 0) {
        float a = 0.f, c = 0.f;
        #pragma unroll
        for (int ww = 0; ww < 4; ww++) { a += rs1[ww]; c += rs2[ww]; }
        atomicAdd(&g_s.S1[b*NK + k], a);
        atomicAdd(&g_s.S2[b*NK + k], c);
    }
}

// ---------------------------------------------------------------------------
// K2: Z blur + weights + reduction; 8 x per thread (uint4 ring = LDG.128,
// doubled per-thread MLP). Warp = 2 y-rows (16 lanes x 8x each); CTA = 128
// thr = 8 rows. grid: (16 ytiles, 4 zchunks, 8 = k+4b) = 512 CTAs.
// Fully unrolled ZC=32 (ring register-renamed). Last CTA finalizes.
// ---------------------------------------------------------------------------
__global__ __launch_bounds__(128)
void k_zred(const float* __restrict__ labels, const float* __restrict__ inputs,
            float* __restrict__ out) {
    const int tid  = threadIdx.x;
    const int warp = tid >> 5, lane = tid & 31;
    const int y  = blockIdx.x * 8 + warp * 2 + (lane >> 4);
    const int x8 = (lane & 15) * 8;
    const int z0 = blockIdx.y * ZC;
    const int k  = blockIdx.z & 3;
    const int b  = blockIdx.z >> 2;
    const int bk = b*NK + k;

    const float Nf = (float)VOL;
    const float mean = (g_s.S1[bk] / Nf) / (g_s.S2[bk] / Nf + 1e-5f);

    const __half*  bp = g_blur + (size_t)bk * VOL + y * 128 + x8;
    const float4*  lp = (const float4*)(labels + (size_t)bk * VOL + y * 128 + x8);
    const float4*  ip = (const float4*)(inputs + (size_t)b  * VOL + y * 128 + x8);

    uint4 v[9];
    #pragma unroll
    for (int j = 0; j < 9; j++) {
        int zz = z0 - RAD + j;
        v[j] = (zz >= 0 && zz < DIMZ)
             ? *reinterpret_cast<const uint4*>(bp + (size_t)zz * HW)
             : make_uint4(0u, 0u, 0u, 0u);
    }

    float num = 0.f, den = 0.f;

    #pragma unroll
    for (int cz = 0; cz < ZC; cz++) {
        int z = z0 + cz;
        __half2 b0 = u2h(0u), b1 = u2h(0u), b2 = u2h(0u), b3 = u2h(0u);
        #pragma unroll
        for (int j = 0; j < 9; j++) {
            __half2 g = u2h(c_gh2[j]);
            b0 = __hfma2(g, u2h(v[j].x), b0);
            b1 = __hfma2(g, u2h(v[j].y), b1);
            b2 = __hfma2(g, u2h(v[j].z), b2);
            b3 = __hfma2(g, u2h(v[j].w), b3);
        }
        float2 f0 = __half22float2(b0);
        float2 f1 = __half22float2(b1);
        float2 f2 = __half22float2(b2);
        float2 f3 = __half22float2(b3);

        float4 la = __ldcs(lp + (size_t)z * (HW/4));
        float4 lb = __ldcs(lp + (size_t)z * (HW/4) + 1);
        float4 ia = ip[(size_t)z * (HW/4)];
        float4 ib = ip[(size_t)z * (HW/4) + 1];

        {
            float d = ia.x - mean, d2 = d*d, wv = __expf(-d2*d2);
            num = fmaf(f0.x * la.x, wv, num); den = fmaf(f0.x, wv, den);
        }
        {
            float d = ia.y - mean, d2 = d*d, wv = __expf(-d2*d2);
            num = fmaf(f0.y * la.y, wv, num); den = fmaf(f0.y, wv, den);
        }
        {
            float d = ia.z - mean, d2 = d*d, wv = __expf(-d2*d2);
            num = fmaf(f1.x * la.z, wv, num); den = fmaf(f1.x, wv, den);
        }
        {
            float d = ia.w - mean, d2 = d*d, wv = __expf(-d2*d2);
            num = fmaf(f1.y * la.w, wv, num); den = fmaf(f1.y, wv, den);
        }
        {
            float d = ib.x - mean, d2 = d*d, wv = __expf(-d2*d2);
            num = fmaf(f2.x * lb.x, wv, num); den = fmaf(f2.x, wv, den);
        }
        {
            float d = ib.y - mean, d2 = d*d, wv = __expf(-d2*d2);
            num = fmaf(f2.y * lb.y, wv, num); den = fmaf(f2.y, wv, den);
        }
        {
            float d = ib.z - mean, d2 = d*d, wv = __expf(-d2*d2);
            num = fmaf(f3.x * lb.z, wv, num); den = fmaf(f3.x, wv, den);
        }
        {
            float d = ib.w - mean, d2 = d*d, wv = __expf(-d2*d2);
            num = fmaf(f3.y * lb.w, wv, num); den = fmaf(f3.y, wv, den);
        }

        #pragma unroll
        for (int j = 0; j < 8; j++) v[j] = v[j + 1];
        int zn = z + RAD + 1;
        v[8] = (zn < DIMZ)
             ? *reinterpret_cast<const uint4*>(bp + (size_t)zn * HW)
             : make_uint4(0u, 0u, 0u, 0u);
    }

    // CTA reduction -> 2 double atomics.
    #pragma unroll
    for (int o = 16; o; o >>= 1) {
        num += __shfl_down_sync(0xffffffffu, num, o);
        den += __shfl_down_sync(0xffffffffu, den, o);
    }
    __shared__ float rn[4], rd[4];
    if (lane == 0) { rn[warp] = num; rd[warp] = den; }
    __syncthreads();
    __shared__ bool is_last;
    if (tid == 0) {
        double a = 0.0, c = 0.0;
        #pragma unroll
        for (int w = 0; w < 4; w++) { a += (double)rn[w]; c += (double)rd[w]; }
        atomicAdd(&g_s.num[k], a);
        atomicAdd(&g_s.den[k], c);
        __threadfence();
        int done = atomicAdd(&g_s.ctr, 1);
        is_last = (done == K2_CTAS - 1);
    }
    __syncthreads();

    if (is_last && tid == 0) {
        __threadfence();
        float loss = 0.f;
        #pragma unroll
        for (int kk = 0; kk < NK; kk++) {
            float n = (float)g_s.num[kk];
            float d = (float)g_s.den[kk];
            loss += fabsf(n / (d + 1e-6f));
        }
        out[0] = (float)NK - loss;
    }
}

extern "C" void kernel_launch(void* const* d_in, const int* in_sizes, int n_in,
                              void* d_out, int out_size) {
    const float* labels;
    const float* inputs;
    if (in_sizes[0] == NB*NK*VOL) {
        labels = (const float*)d_in[0];
        inputs = (const float*)d_in[1];
    } else {
        labels = (const float*)d_in[1];
        inputs = (const float*)d_in[0];
    }

    void* scal_ptr = nullptr;
    cudaGetSymbolAddress(&scal_ptr, g_s);
    cudaMemsetAsync(scal_ptr, 0, sizeof(Scal));

    dim3 g1(128, 4, 2);
    k_xyblur<<<g1, 128>>>(labels, inputs);

    dim3 g2(16, 4, 8);
    k_zred<<<g2, 128>>>(labels, inputs, (float*)d_out);
}

// round 16
// speedup vs baseline: 1.0644x; 1.0644x over previous
#include <cuda_runtime.h>
#include <cuda_fp16.h>
#include <math.h>

#define DIMZ 128
#define HW   (128*128)
#define VOL  (128*128*128)
#define NB   2
#define NK   4
#define RAD  4
#define ZC   32                 // z-chunk in K2 (halo ratio 1.25)
#define K2_CTAS (32*4*8)        // ytiles * zchunks * (k*b)

// 32 MB fp16 scratch for the XY-blurred labels field.
__device__ __align__(16) __half g_blur[NB*NK*VOL];

struct Scal {
    float  S1[NB*NK];
    float  S2[NB*NK];
    double num[NK];
    double den[NK];
    int    ctr;
};
__device__ Scal g_s;

// gauss taps: exp(-x^2/(2*25)) for x=-4..4 (fp32, for x-blur + packing)
__constant__ float c_g[9] = {
    0.72614904f, 0.83527021f, 0.92311635f, 0.98019867f, 1.0f,
    0.98019867f, 0.92311635f, 0.83527021f, 0.72614904f
};
// same taps as packed half2 bit patterns (round-to-nearest fp16)
__constant__ unsigned c_gh2[9] = {
    0x39CF39CFu, 0x3AAF3AAFu, 0x3B633B63u, 0x3BD73BD7u, 0x3C003C00u,
    0x3BD73BD7u, 0x3B633B63u, 0x3AAF3AAFu, 0x39CF39CFu
};

__device__ __forceinline__ __half2 u2h(unsigned u) {
    return *reinterpret_cast<__half2*>(&u);
}
__device__ __forceinline__ unsigned h2u(__half2 h) {
    return *reinterpret_cast<unsigned*>(&h);
}

__device__ __forceinline__ float blur9(const float* a) {
    float acc = 0.f;
    #pragma unroll
    for (int t = 0; t < 9; t++) acc = fmaf(c_g[t], a[t], acc);
    return acc;
}

// Load labels row gy (zero outside volume), accumulate mean sums on uniquely
// owned center rows, return the X-blurred float4 for this lane (x = 4*lane)
// using lane shuffles for the +-4 halo. No shared memory.
__device__ __forceinline__ float4 xblur_load(
    int gy, const float4* __restrict__ lp4, const float4* __restrict__ ip4,
    int lane, int y0, float& s1, float& s2)
{
    float4 c = make_float4(0.f, 0.f, 0.f, 0.f);
    if (gy >= 0 && gy < 128) {
        c = __ldcs(lp4 + gy * 32 + lane);
        if (gy >= y0 && gy < y0 + 32) {
            float4 u = ip4[gy * 32 + lane];
            s1 += c.x*u.x + c.y*u.y + c.z*u.z + c.w*u.w;
            s2 += c.x + c.y + c.z + c.w;
        }
    }
    float a[12];
    a[0] = __shfl_up_sync(0xffffffffu, c.x, 1);
    a[1] = __shfl_up_sync(0xffffffffu, c.y, 1);
    a[2] = __shfl_up_sync(0xffffffffu, c.z, 1);
    a[3] = __shfl_up_sync(0xffffffffu, c.w, 1);
    if (lane == 0) { a[0] = a[1] = a[2] = a[3] = 0.f; }
    a[4] = c.x; a[5] = c.y; a[6] = c.z; a[7] = c.w;
    a[8]  = __shfl_down_sync(0xffffffffu, c.x, 1);
    a[9]  = __shfl_down_sync(0xffffffffu, c.y, 1);
    a[10] = __shfl_down_sync(0xffffffffu, c.z, 1);
    a[11] = __shfl_down_sync(0xffffffffu, c.w, 1);
    if (lane == 31) { a[8] = a[9] = a[10] = a[11] = 0.f; }
    float4 r;
    r.x = blur9(a + 0);
    r.y = blur9(a + 1);
    r.z = blur9(a + 2);
    r.w = blur9(a + 3);
    return r;
}

// Pack an fp32 x-blurred float4 into 2 half2 (uint2).
__device__ __forceinline__ uint2 pack4(float4 r) {
    uint2 p;
    p.x = h2u(__floats2half2_rn(r.x, r.y));
    p.y = h2u(__floats2half2_rn(r.z, r.w));
    return p;
}

// ---------------------------------------------------------------------------
// K1: XY blur of labels (R12 body/shape) with the y-loop FULLY unrolled so
// the 9-deep uint2 ring is register-renamed instead of MOV-shifted (same
// lever that won on K2 in R11). CTA = 128 thr = 4 warps = 4 y-quarters of
// ONE z-slice. grid: (128 z, 4 k, 2 b) = 1024 CTAs.
// ---------------------------------------------------------------------------
__global__ __launch_bounds__(128)
void k_xyblur(const float* __restrict__ labels, const float* __restrict__ inputs) {
    const int tid = threadIdx.x;
    const int warp = tid >> 5, lane = tid & 31;
    const int z  = blockIdx.x;
    const int y0 = warp * 32;
    const int k  = blockIdx.y;
    const int b  = blockIdx.z;
    const int x4 = lane * 4;

    const float4* lp4 = (const float4*)(labels + (size_t)(b*NK + k) * VOL + (size_t)z * HW);
    const float4* ip4 = (const float4*)(inputs + (size_t)b * VOL + (size_t)z * HW);
    __half* op = g_blur + (size_t)(b*NK + k) * VOL + (size_t)z * HW;

    float s1 = 0.f, s2 = 0.f;
    uint2 w[9];
    #pragma unroll
    for (int j = 0; j < 9; j++)
        w[j] = pack4(xblur_load(y0 - RAD + j, lp4, ip4, lane, y0, s1, s2));

    #pragma unroll
    for (int i = 0; i < 32; i++) {
        __half2 b0 = u2h(0u), b1 = u2h(0u);
        #pragma unroll
        for (int j = 0; j < 9; j++) {
            __half2 g = u2h(c_gh2[j]);
            b0 = __hfma2(g, u2h(w[j].x), b0);
            b1 = __hfma2(g, u2h(w[j].y), b1);
        }
        uint2 pk; pk.x = h2u(b0); pk.y = h2u(b1);
        *reinterpret_cast<uint2*>(op + (y0 + i) * 128 + x4) = pk;

        #pragma unroll
        for (int j = 0; j < 8; j++) w[j] = w[j + 1];
        w[8] = pack4(xblur_load(y0 + i + RAD + 1, lp4, ip4, lane, y0, s1, s2));
    }

    #pragma unroll
    for (int o = 16; o; o >>= 1) {
        s1 += __shfl_down_sync(0xffffffffu, s1, o);
        s2 += __shfl_down_sync(0xffffffffu, s2, o);
    }
    __shared__ float rs1[4], rs2[4];
    if (lane == 0) { rs1[warp] = s1; rs2[warp] = s2; }
    __syncthreads();
    if (tid == 0) {
        float a = 0.f, c = 0.f;
        #pragma unroll
        for (int ww = 0; ww < 4; ww++) { a += rs1[ww]; c += rs2[ww]; }
        atomicAdd(&g_s.S1[b*NK + k], a);
        atomicAdd(&g_s.S2[b*NK + k], c);
    }
}

// ---------------------------------------------------------------------------
// K2: Z blur with rolling half2 window (HFMA2), fused weights + reduction.
//     num = sum B(p)*p*w,  den = sum B(p)*w   (blur operator self-adjoint).
// R12 body/shape (measured best): fully-unrolled ZC=32, 4 x per thread,
// CTA = 128 thr = 4 warps = 4 y-rows. grid: (32, 4, 8) = 1024 CTAs.
// Last CTA finalizes.
// ---------------------------------------------------------------------------
__global__ __launch_bounds__(128)
void k_zred(const float* __restrict__ labels, const float* __restrict__ inputs,
            float* __restrict__ out) {
    const int tid  = threadIdx.x;
    const int warp = tid >> 5, lane = tid & 31;
    const int y  = blockIdx.x * 4 + warp;
    const int z0 = blockIdx.y * ZC;
    const int k  = blockIdx.z & 3;
    const int b  = blockIdx.z >> 2;
    const int bk = b*NK + k;
    const int x4 = lane * 4;

    const float Nf = (float)VOL;
    const float mean = (g_s.S1[bk] / Nf) / (g_s.S2[bk] / Nf + 1e-5f);

    const __half*  bp = g_blur + (size_t)bk * VOL + y * 128 + x4;
    const float4*  lp = (const float4*)(labels + (size_t)bk * VOL + y * 128 + x4);
    const float4*  ip = (const float4*)(inputs + (size_t)b  * VOL + y * 128 + x4);

    uint2 v[9];
    #pragma unroll
    for (int j = 0; j < 9; j++) {
        int zz = z0 - RAD + j;
        v[j] = (zz >= 0 && zz < DIMZ)
             ? *reinterpret_cast<const uint2*>(bp + (size_t)zz * HW)
             : make_uint2(0u, 0u);
    }

    float num = 0.f, den = 0.f;

    #pragma unroll
    for (int cz = 0; cz < ZC; cz++) {
        int z = z0 + cz;
        __half2 b0 = u2h(0u), b1 = u2h(0u);
        #pragma unroll
        for (int j = 0; j < 9; j++) {
            __half2 g = u2h(c_gh2[j]);
            b0 = __hfma2(g, u2h(v[j].x), b0);
            b1 = __hfma2(g, u2h(v[j].y), b1);
        }
        float2 f0 = __half22float2(b0);
        float2 f1 = __half22float2(b1);

        float4 lab = __ldcs(lp + (size_t)z * (HW/4));
        float4 inp = ip[(size_t)z * (HW/4)];

        {
            float d = inp.x - mean, d2 = d*d, wv = __expf(-d2*d2);
            num = fmaf(f0.x * lab.x, wv, num); den = fmaf(f0.x, wv, den);
        }
        {
            float d = inp.y - mean, d2 = d*d, wv = __expf(-d2*d2);
            num = fmaf(f0.y * lab.y, wv, num); den = fmaf(f0.y, wv, den);
        }
        {
            float d = inp.z - mean, d2 = d*d, wv = __expf(-d2*d2);
            num = fmaf(f1.x * lab.z, wv, num); den = fmaf(f1.x, wv, den);
        }
        {
            float d = inp.w - mean, d2 = d*d, wv = __expf(-d2*d2);
            num = fmaf(f1.y * lab.w, wv, num); den = fmaf(f1.y, wv, den);
        }

        #pragma unroll
        for (int j = 0; j < 8; j++) v[j] = v[j + 1];
        int zn = z + RAD + 1;
        v[8] = (zn < DIMZ)
             ? *reinterpret_cast<const uint2*>(bp + (size_t)zn * HW)
             : make_uint2(0u, 0u);
    }

    // CTA reduction -> 2 double atomics.
    #pragma unroll
    for (int o = 16; o; o >>= 1) {
        num += __shfl_down_sync(0xffffffffu, num, o);
        den += __shfl_down_sync(0xffffffffu, den, o);
    }
    __shared__ float rn[4], rd[4];
    if (lane == 0) { rn[warp] = num; rd[warp] = den; }
    __syncthreads();
    __shared__ bool is_last;
    if (tid == 0) {
        double a = 0.0, c = 0.0;
        #pragma unroll
        for (int w = 0; w < 4; w++) { a += (double)rn[w]; c += (double)rd[w]; }
        atomicAdd(&g_s.num[k], a);
        atomicAdd(&g_s.den[k], c);
        __threadfence();
        int done = atomicAdd(&g_s.ctr, 1);
        is_last = (done == K2_CTAS - 1);
    }
    __syncthreads();

    if (is_last && tid == 0) {
        __threadfence();
        float loss = 0.f;
        #pragma unroll
        for (int kk = 0; kk < NK; kk++) {
            float n = (float)g_s.num[kk];
            float d = (float)g_s.den[kk];
            loss += fabsf(n / (d + 1e-6f));
        }
        out[0] = (float)NK - loss;
    }
}

extern "C" void kernel_launch(void* const* d_in, const int* in_sizes, int n_in,
                              void* d_out, int out_size) {
    const float* labels;
    const float* inputs;
    if (in_sizes[0] == NB*NK*VOL) {
        labels = (const float*)d_in[0];
        inputs = (const float*)d_in[1];
    } else {
        labels = (const float*)d_in[1];
        inputs = (const float*)d_in[0];
    }

    void* scal_ptr = nullptr;
    cudaGetSymbolAddress(&scal_ptr, g_s);
    cudaMemsetAsync(scal_ptr, 0, sizeof(Scal));

    dim3 g1(128, 4, 2);
    k_xyblur<<<g1, 128>>>(labels, inputs);

    dim3 g2(32, 4, 8);
    k_zred<<<g2, 128>>>(labels, inputs, (float*)d_out);
}